// round 5
// baseline (speedup 1.0000x reference)
#include <cuda_runtime.h>
#include <cuda_bf16.h>
#include <cstdint>

// DEQ via warp-level bf16 HMMA (mma.sync.m16n8k16): z <- tanh(c + z B^T),
// 5 tanh applications (z1 = tanh(c), then 4 GEMM iterations; last fuses y = z.h).
// One CTA = 128 batch rows, 8 warps, each warp owns a 16-row band with z kept
// in A-operand register fragments across iterations (acc layout == A layout).
// B (bf16) and c (fp32) in SMEM; no __syncthreads in the iteration loop.
// R5: ldmatrix interleaved with mma (8 live B regs, not 32) -> no spills.

#define THREADS 256
#define LDB_B   272        // bytes per B row (136 bf16: 128 + pad -> conflict-free LDSM)
#define LDC_F   132        // floats per c row (528 B: 128 + pad)
#define SM_B    0          // 128 * 272                = 34816 B
#define SM_C    34816      // 128 * 528                = 67584 B
#define SM_H    102400     // 128 f32                  =   512 B
#define SM_TOTAL 102912

__device__ __forceinline__ float tanh_exact(float v) {
    float e = __expf(2.0f * v);
    return 1.0f - __fdividef(2.0f, e + 1.0f);
}
__device__ __forceinline__ float tanh_apx(float v) {
    float r; asm("tanh.approx.f32 %0, %1;" : "=f"(r) : "f"(v)); return r;
}
// pack {lo, hi} floats into bf16x2 (first src operand -> high half)
__device__ __forceinline__ uint32_t packlh(float lo, float hi) {
    uint32_t r;
    asm("cvt.rn.satfinite.bf16x2.f32 %0, %1, %2;" : "=r"(r) : "f"(hi), "f"(lo));
    return r;
}
__device__ __forceinline__ void mma16816(float* d, const uint32_t* a,
                                         uint32_t b0, uint32_t b1) {
    asm volatile(
        "mma.sync.aligned.m16n8k16.row.col.f32.bf16.bf16.f32 "
        "{%0,%1,%2,%3}, {%4,%5,%6,%7}, {%8,%9}, {%0,%1,%2,%3};"
        : "+f"(d[0]), "+f"(d[1]), "+f"(d[2]), "+f"(d[3])
        : "r"(a[0]), "r"(a[1]), "r"(a[2]), "r"(a[3]), "r"(b0), "r"(b1));
}
__device__ __forceinline__ void ldsm4(uint32_t* r, uint32_t addr) {
    asm volatile("ldmatrix.sync.aligned.m8n8.x4.shared.b16 {%0,%1,%2,%3}, [%4];"
                 : "=r"(r[0]), "=r"(r[1]), "=r"(r[2]), "=r"(r[3]) : "r"(addr));
}

// One GEMM iteration: out = z_cur * B^T; z_next = tanh(c + out)  (or y-reduce on LAST)
template<bool LAST>
__device__ __forceinline__ void gemm_iter(
    uint32_t bb,                 // per-thread LDSM base address (shared space)
    const float2* c2w,           // c pairs, this thread's row (qr)
    const float2* c2w8,          // c pairs, row qr+8
    const float2* h2,            // h weights as pairs
    const uint32_t A[8][4], uint32_t An[8][4],
    float& y0, float& y1, int qc)
{
    #pragma unroll
    for (int ntp = 0; ntp < 8; ++ntp) {
        const uint32_t b0a = bb + (uint32_t)(2 * ntp)     * (8 * LDB_B);
        const uint32_t b1a = bb + (uint32_t)(2 * ntp + 1) * (8 * LDB_B);
        float acc0[4] = {0.f, 0.f, 0.f, 0.f};
        float acc1[4] = {0.f, 0.f, 0.f, 0.f};
        #pragma unroll
        for (int l = 0; l < 4; ++l) {       // each l covers k-tiles 2l, 2l+1
            uint32_t b0[4], b1[4];
            ldsm4(b0, b0a + l * 64);
            ldsm4(b1, b1a + l * 64);
            mma16816(acc0, A[2 * l],     b0[0], b0[1]);
            mma16816(acc0, A[2 * l + 1], b0[2], b0[3]);
            mma16816(acc1, A[2 * l],     b1[0], b1[1]);
            mma16816(acc1, A[2 * l + 1], b1[2], b1[3]);
        }
        #pragma unroll
        for (int h = 0; h < 2; ++h) {
            const int nt = 2 * ntp + h;
            const float* acc = h ? acc1 : acc0;
            float2 cl0 = c2w [4 * nt + qc];
            float2 cl1 = c2w8[4 * nt + qc];
            float p0 = acc[0] + cl0.x, p1 = acc[1] + cl0.y;
            float p2 = acc[2] + cl1.x, p3 = acc[3] + cl1.y;
            if (LAST) {
                float2 hv = h2[4 * nt + qc];
                y0 += hv.x * tanh_exact(p0) + hv.y * tanh_exact(p1);
                y1 += hv.x * tanh_exact(p2) + hv.y * tanh_exact(p3);
            } else {
                An[ntp][2 * h + 0] = packlh(tanh_apx(p0), tanh_apx(p1));
                An[ntp][2 * h + 1] = packlh(tanh_apx(p2), tanh_apx(p3));
            }
        }
    }
}

__global__ void __launch_bounds__(THREADS, 2)
deq_mma_kernel(const float* __restrict__ x,
               const float* __restrict__ Aw,
               const float* __restrict__ Ab,
               const float* __restrict__ Bw,
               const float* __restrict__ Bb,
               const float* __restrict__ hw,
               const float* __restrict__ hb,
               float* __restrict__ out)
{
    extern __shared__ char smem[];
    const int tid  = threadIdx.x;
    const int row0 = blockIdx.x * 128;

    // ---- stage B as bf16, padded rows (row = n-index i, col = k-index j) ----
    #pragma unroll 4
    for (int idx = tid; idx < 128 * 128; idx += THREADS) {
        int i = idx >> 7, j = idx & 127;
        *(__nv_bfloat16*)(smem + SM_B + i * LDB_B + j * 2) = __float2bfloat16(Bw[idx]);
    }
    if (tid < 128) ((float*)(smem + SM_H))[tid] = hw[tid];

    // ---- c = x A^T + (A_b + B_b)  (thread = half row) ----
    {
        int r  = tid >> 1;
        int i0 = (tid & 1) << 6;
        float4 xv = ((const float4*)x)[row0 + r];
        float* crow = (float*)(smem + SM_C) + r * LDC_F;
        #pragma unroll 8
        for (int k = 0; k < 64; ++k) {
            int i = i0 + k;
            float4 a = ((const float4*)Aw)[i];
            crow[i] = Ab[i] + Bb[i]
                    + xv.x * a.x + xv.y * a.y + xv.z * a.z + xv.w * a.w;
        }
    }
    __syncthreads();

    // ---- per-warp fragment setup ----
    const int lane = tid & 31, wid = tid >> 5;
    const int qr = lane >> 2, qc = lane & 3;
    const int rb = wid * 16;
    const float2* c2  = (const float2*)(smem + SM_C);
    const float2* c2w  = c2 + (rb + qr) * (LDC_F / 2);
    const float2* c2w8 = c2w + 8 * (LDC_F / 2);
    const float2* h2  = (const float2*)(smem + SM_H);
    const uint32_t sb = (uint32_t)__cvta_generic_to_shared(smem);
    const uint32_t bb = sb + SM_B + (uint32_t)(lane & 7) * LDB_B + (uint32_t)(lane >> 3) * 16;

    // ---- z1 = tanh(c) into A fragments ----
    uint32_t A[8][4], An[8][4];
    #pragma unroll
    for (int kt = 0; kt < 8; ++kt) {
        float2 u0 = c2w [8 * kt + qc];
        float2 u1 = c2w8[8 * kt + qc];
        float2 u2 = c2w [8 * kt + 4 + qc];
        float2 u3 = c2w8[8 * kt + 4 + qc];
        A[kt][0] = packlh(tanh_apx(u0.x), tanh_apx(u0.y));
        A[kt][1] = packlh(tanh_apx(u1.x), tanh_apx(u1.y));
        A[kt][2] = packlh(tanh_apx(u2.x), tanh_apx(u2.y));
        A[kt][3] = packlh(tanh_apx(u3.x), tanh_apx(u3.y));
    }

    // ---- 4 GEMM iterations (z2..z5), last fuses y = z5 . h ----
    float y0 = 0.f, y1 = 0.f;
    gemm_iter<false>(bb, c2w, c2w8, h2, A,  An, y0, y1, qc);
    gemm_iter<false>(bb, c2w, c2w8, h2, An, A,  y0, y1, qc);
    gemm_iter<false>(bb, c2w, c2w8, h2, A,  An, y0, y1, qc);
    gemm_iter<true >(bb, c2w, c2w8, h2, An, A,  y0, y1, qc);

    // ---- reduce y across the 4 lanes sharing a row, write out ----
    y0 += __shfl_xor_sync(0xffffffffu, y0, 1);
    y0 += __shfl_xor_sync(0xffffffffu, y0, 2);
    y1 += __shfl_xor_sync(0xffffffffu, y1, 1);
    y1 += __shfl_xor_sync(0xffffffffu, y1, 2);
    if (qc == 0) {
        float hb0 = hb[0];
        out[row0 + rb + qr]     = y0 + hb0;
        out[row0 + rb + qr + 8] = y1 + hb0;
    }
}

extern "C" void kernel_launch(void* const* d_in, const int* in_sizes, int n_in,
                              void* d_out, int out_size) {
    const float* x  = (const float*)d_in[0];
    const float* Aw = (const float*)d_in[1];
    const float* Ab = (const float*)d_in[2];
    const float* Bw = (const float*)d_in[3];
    const float* Bb = (const float*)d_in[4];
    const float* hw = (const float*)d_in[5];
    const float* hb = (const float*)d_in[6];
    float* out = (float*)d_out;

    int batch = in_sizes[0] / 4;     // x is [batch, 4]
    int grid  = batch / 128;         // 1024

    cudaFuncSetAttribute(deq_mma_kernel,
                         cudaFuncAttributeMaxDynamicSharedMemorySize,
                         SM_TOTAL);
    deq_mma_kernel<<<grid, THREADS, SM_TOTAL>>>(x, Aw, Ab, Bw, Bb, hw, hb, out);
}

// round 6
// speedup vs baseline: 2.5719x; 2.5719x over previous
#include <cuda_runtime.h>
#include <cuda_bf16.h>
#include <cstdint>

// DEQ via warp-level bf16 HMMA (mma.sync.m16n8k16): z <- tanh(c + z B^T),
// 5 tanh applications (z1 = tanh(c), then 4 GEMM iterations; last fuses y = z.h).
// One CTA = 128 batch rows, 8 warps, each warp owns a 16-row band with z kept
// in A-operand register fragments across iterations (acc layout == A layout).
// B (bf16) and c (fp32) in SMEM; no __syncthreads in the iteration loop.
// R6: __launch_bounds__(256,1) -> 255-reg budget, no spills (R4/R5 were
// spilling ~1.3GB to local at the 128-reg cap; DRAM was 46% busy on a
// compute kernel).

#define THREADS 256
#define LDB_B   272        // bytes per B row (136 bf16: 128 + pad -> conflict-free LDSM)
#define LDC_F   132        // floats per c row (528 B: 128 + pad)
#define SM_B    0          // 128 * 272                = 34816 B
#define SM_C    34816      // 128 * 528                = 67584 B
#define SM_H    102400     // 128 f32                  =   512 B
#define SM_TOTAL 102912

__device__ __forceinline__ float tanh_exact(float v) {
    float e = __expf(2.0f * v);
    return 1.0f - __fdividef(2.0f, e + 1.0f);
}
__device__ __forceinline__ float tanh_apx(float v) {
    float r; asm("tanh.approx.f32 %0, %1;" : "=f"(r) : "f"(v)); return r;
}
// pack {lo, hi} floats into bf16x2 (first src operand -> high half)
__device__ __forceinline__ uint32_t packlh(float lo, float hi) {
    uint32_t r;
    asm("cvt.rn.satfinite.bf16x2.f32 %0, %1, %2;" : "=r"(r) : "f"(hi), "f"(lo));
    return r;
}
__device__ __forceinline__ void mma16816(float* d, const uint32_t* a,
                                         uint32_t b0, uint32_t b1) {
    asm volatile(
        "mma.sync.aligned.m16n8k16.row.col.f32.bf16.bf16.f32 "
        "{%0,%1,%2,%3}, {%4,%5,%6,%7}, {%8,%9}, {%0,%1,%2,%3};"
        : "+f"(d[0]), "+f"(d[1]), "+f"(d[2]), "+f"(d[3])
        : "r"(a[0]), "r"(a[1]), "r"(a[2]), "r"(a[3]), "r"(b0), "r"(b1));
}
__device__ __forceinline__ void ldsm4(uint32_t* r, uint32_t addr) {
    asm volatile("ldmatrix.sync.aligned.m8n8.x4.shared.b16 {%0,%1,%2,%3}, [%4];"
                 : "=r"(r[0]), "=r"(r[1]), "=r"(r[2]), "=r"(r[3]) : "r"(addr));
}

// One GEMM iteration: out = z_cur * B^T; z_next = tanh(c + out)  (or y-reduce on LAST)
template<bool LAST>
__device__ __forceinline__ void gemm_iter(
    uint32_t bb,                 // per-thread LDSM base address (shared space)
    const float2* c2w,           // c pairs, this thread's row (qr)
    const float2* c2w8,          // c pairs, row qr+8
    const float2* h2,            // h weights as pairs
    const uint32_t A[8][4], uint32_t An[8][4],
    float& y0, float& y1, int qc)
{
    #pragma unroll
    for (int ntp = 0; ntp < 8; ++ntp) {
        const uint32_t b0a = bb + (uint32_t)(2 * ntp)     * (8 * LDB_B);
        const uint32_t b1a = bb + (uint32_t)(2 * ntp + 1) * (8 * LDB_B);
        float acc0[4] = {0.f, 0.f, 0.f, 0.f};
        float acc1[4] = {0.f, 0.f, 0.f, 0.f};
        #pragma unroll
        for (int l = 0; l < 4; ++l) {       // each l covers k-tiles 2l, 2l+1
            uint32_t b0[4], b1[4];
            ldsm4(b0, b0a + l * 64);
            ldsm4(b1, b1a + l * 64);
            mma16816(acc0, A[2 * l],     b0[0], b0[1]);
            mma16816(acc0, A[2 * l + 1], b0[2], b0[3]);
            mma16816(acc1, A[2 * l],     b1[0], b1[1]);
            mma16816(acc1, A[2 * l + 1], b1[2], b1[3]);
        }
        #pragma unroll
        for (int h = 0; h < 2; ++h) {
            const int nt = 2 * ntp + h;
            const float* acc = h ? acc1 : acc0;
            float2 cl0 = c2w [4 * nt + qc];
            float2 cl1 = c2w8[4 * nt + qc];
            float p0 = acc[0] + cl0.x, p1 = acc[1] + cl0.y;
            float p2 = acc[2] + cl1.x, p3 = acc[3] + cl1.y;
            if (LAST) {
                float2 hv = h2[4 * nt + qc];
                y0 += hv.x * tanh_exact(p0) + hv.y * tanh_exact(p1);
                y1 += hv.x * tanh_exact(p2) + hv.y * tanh_exact(p3);
            } else {
                An[ntp][2 * h + 0] = packlh(tanh_apx(p0), tanh_apx(p1));
                An[ntp][2 * h + 1] = packlh(tanh_apx(p2), tanh_apx(p3));
            }
        }
    }
}

__global__ void __launch_bounds__(THREADS, 1)
deq_mma_kernel(const float* __restrict__ x,
               const float* __restrict__ Aw,
               const float* __restrict__ Ab,
               const float* __restrict__ Bw,
               const float* __restrict__ Bb,
               const float* __restrict__ hw,
               const float* __restrict__ hb,
               float* __restrict__ out)
{
    extern __shared__ char smem[];
    const int tid  = threadIdx.x;
    const int row0 = blockIdx.x * 128;

    // ---- stage B as bf16, padded rows (row = n-index i, col = k-index j) ----
    #pragma unroll 4
    for (int idx = tid; idx < 128 * 128; idx += THREADS) {
        int i = idx >> 7, j = idx & 127;
        *(__nv_bfloat16*)(smem + SM_B + i * LDB_B + j * 2) = __float2bfloat16(Bw[idx]);
    }
    if (tid < 128) ((float*)(smem + SM_H))[tid] = hw[tid];

    // ---- c = x A^T + (A_b + B_b)  (thread = half row) ----
    {
        int r  = tid >> 1;
        int i0 = (tid & 1) << 6;
        float4 xv = ((const float4*)x)[row0 + r];
        float* crow = (float*)(smem + SM_C) + r * LDC_F;
        #pragma unroll 8
        for (int k = 0; k < 64; ++k) {
            int i = i0 + k;
            float4 a = ((const float4*)Aw)[i];
            crow[i] = Ab[i] + Bb[i]
                    + xv.x * a.x + xv.y * a.y + xv.z * a.z + xv.w * a.w;
        }
    }
    __syncthreads();

    // ---- per-warp fragment setup ----
    const int lane = tid & 31, wid = tid >> 5;
    const int qr = lane >> 2, qc = lane & 3;
    const int rb = wid * 16;
    const float2* c2  = (const float2*)(smem + SM_C);
    const float2* c2w  = c2 + (rb + qr) * (LDC_F / 2);
    const float2* c2w8 = c2w + 8 * (LDC_F / 2);
    const float2* h2  = (const float2*)(smem + SM_H);
    const uint32_t sb = (uint32_t)__cvta_generic_to_shared(smem);
    const uint32_t bb = sb + SM_B + (uint32_t)(lane & 7) * LDB_B + (uint32_t)(lane >> 3) * 16;

    // ---- z1 = tanh(c) into A fragments ----
    uint32_t A[8][4], An[8][4];
    #pragma unroll
    for (int kt = 0; kt < 8; ++kt) {
        float2 u0 = c2w [8 * kt + qc];
        float2 u1 = c2w8[8 * kt + qc];
        float2 u2 = c2w [8 * kt + 4 + qc];
        float2 u3 = c2w8[8 * kt + 4 + qc];
        A[kt][0] = packlh(tanh_apx(u0.x), tanh_apx(u0.y));
        A[kt][1] = packlh(tanh_apx(u1.x), tanh_apx(u1.y));
        A[kt][2] = packlh(tanh_apx(u2.x), tanh_apx(u2.y));
        A[kt][3] = packlh(tanh_apx(u3.x), tanh_apx(u3.y));
    }

    // ---- 4 GEMM iterations (z2..z5), last fuses y = z5 . h ----
    float y0 = 0.f, y1 = 0.f;
    gemm_iter<false>(bb, c2w, c2w8, h2, A,  An, y0, y1, qc);
    gemm_iter<false>(bb, c2w, c2w8, h2, An, A,  y0, y1, qc);
    gemm_iter<false>(bb, c2w, c2w8, h2, A,  An, y0, y1, qc);
    gemm_iter<true >(bb, c2w, c2w8, h2, An, A,  y0, y1, qc);

    // ---- reduce y across the 4 lanes sharing a row, write out ----
    y0 += __shfl_xor_sync(0xffffffffu, y0, 1);
    y0 += __shfl_xor_sync(0xffffffffu, y0, 2);
    y1 += __shfl_xor_sync(0xffffffffu, y1, 1);
    y1 += __shfl_xor_sync(0xffffffffu, y1, 2);
    if (qc == 0) {
        float hb0 = hb[0];
        out[row0 + rb + qr]     = y0 + hb0;
        out[row0 + rb + qr + 8] = y1 + hb0;
    }
}

extern "C" void kernel_launch(void* const* d_in, const int* in_sizes, int n_in,
                              void* d_out, int out_size) {
    const float* x  = (const float*)d_in[0];
    const float* Aw = (const float*)d_in[1];
    const float* Ab = (const float*)d_in[2];
    const float* Bw = (const float*)d_in[3];
    const float* Bb = (const float*)d_in[4];
    const float* hw = (const float*)d_in[5];
    const float* hb = (const float*)d_in[6];
    float* out = (float*)d_out;

    int batch = in_sizes[0] / 4;     // x is [batch, 4]
    int grid  = batch / 128;         // 1024

    cudaFuncSetAttribute(deq_mma_kernel,
                         cudaFuncAttributeMaxDynamicSharedMemorySize,
                         SM_TOTAL);
    deq_mma_kernel<<<grid, THREADS, SM_TOTAL>>>(x, Aw, Ab, Bw, Bb, hw, hb, out);
}

// round 7
// speedup vs baseline: 3.3820x; 1.3150x over previous
#include <cuda_runtime.h>
#include <cuda_bf16.h>
#include <cstdint>

// DEQ via warp-level bf16 HMMA: z <- tanh(c + z B^T), 4 tanh applications
// (z1 = tanh(c) + 3 GEMM iterations; truncation ~5e-5 << bf16 noise 1e-4),
// then y = z4 . h + hb fused into the last iteration.
// R7: persistent CTAs (grid=148, tile loop) — B/h/Aw staged once per SM;
// 3 GEMM iters instead of 4. Still __launch_bounds__(256,1), 255-reg budget.

#define THREADS 256
#define LDB_B   272        // bytes per B row (136 bf16: 128 + pad, conflict-free LDSM)
#define LDC_F   132        // floats per c row (528 B)
#define SM_B    0          // 128 * 272  = 34816 B
#define SM_C    34816      // 128 * 528  = 67584 B
#define SM_H    102400     // 128 f32    =   512 B
#define SM_AW   102912     // 128 float4 =  2048 B (A_w rows)
#define SM_AB   104960     // 128 f32    =   512 B (A_b + B_b)
#define SM_TOTAL 105472

__device__ __forceinline__ float tanh_exact(float v) {
    float e = __expf(2.0f * v);
    return 1.0f - __fdividef(2.0f, e + 1.0f);
}
__device__ __forceinline__ float tanh_apx(float v) {
    float r; asm("tanh.approx.f32 %0, %1;" : "=f"(r) : "f"(v)); return r;
}
__device__ __forceinline__ uint32_t packlh(float lo, float hi) {
    uint32_t r;
    asm("cvt.rn.satfinite.bf16x2.f32 %0, %1, %2;" : "=r"(r) : "f"(hi), "f"(lo));
    return r;
}
__device__ __forceinline__ void mma16816(float* d, const uint32_t* a,
                                         uint32_t b0, uint32_t b1) {
    asm volatile(
        "mma.sync.aligned.m16n8k16.row.col.f32.bf16.bf16.f32 "
        "{%0,%1,%2,%3}, {%4,%5,%6,%7}, {%8,%9}, {%0,%1,%2,%3};"
        : "+f"(d[0]), "+f"(d[1]), "+f"(d[2]), "+f"(d[3])
        : "r"(a[0]), "r"(a[1]), "r"(a[2]), "r"(a[3]), "r"(b0), "r"(b1));
}
__device__ __forceinline__ void ldsm4(uint32_t* r, uint32_t addr) {
    asm volatile("ldmatrix.sync.aligned.m8n8.x4.shared.b16 {%0,%1,%2,%3}, [%4];"
                 : "=r"(r[0]), "=r"(r[1]), "=r"(r[2]), "=r"(r[3]) : "r"(addr));
}

// One GEMM iteration: out = z_cur * B^T; z_next = tanh(c + out) (or y-reduce on LAST)
template<bool LAST>
__device__ __forceinline__ void gemm_iter(
    uint32_t bb, const float2* c2w, const float2* c2w8, const float2* h2,
    const uint32_t A[8][4], uint32_t An[8][4],
    float& y0, float& y1, int qc)
{
    #pragma unroll
    for (int ntp = 0; ntp < 8; ++ntp) {
        const uint32_t b0a = bb + (uint32_t)(2 * ntp)     * (8 * LDB_B);
        const uint32_t b1a = bb + (uint32_t)(2 * ntp + 1) * (8 * LDB_B);
        float acc0[4] = {0.f, 0.f, 0.f, 0.f};
        float acc1[4] = {0.f, 0.f, 0.f, 0.f};
        #pragma unroll
        for (int l = 0; l < 4; ++l) {
            uint32_t b0[4], b1[4];
            ldsm4(b0, b0a + l * 64);
            ldsm4(b1, b1a + l * 64);
            mma16816(acc0, A[2 * l],     b0[0], b0[1]);
            mma16816(acc0, A[2 * l + 1], b0[2], b0[3]);
            mma16816(acc1, A[2 * l],     b1[0], b1[1]);
            mma16816(acc1, A[2 * l + 1], b1[2], b1[3]);
        }
        #pragma unroll
        for (int h = 0; h < 2; ++h) {
            const int nt = 2 * ntp + h;
            const float* acc = h ? acc1 : acc0;
            float2 cl0 = c2w [4 * nt + qc];
            float2 cl1 = c2w8[4 * nt + qc];
            float p0 = acc[0] + cl0.x, p1 = acc[1] + cl0.y;
            float p2 = acc[2] + cl1.x, p3 = acc[3] + cl1.y;
            if (LAST) {
                float2 hv = h2[4 * nt + qc];
                y0 += hv.x * tanh_exact(p0) + hv.y * tanh_exact(p1);
                y1 += hv.x * tanh_exact(p2) + hv.y * tanh_exact(p3);
            } else {
                An[ntp][2 * h + 0] = packlh(tanh_apx(p0), tanh_apx(p1));
                An[ntp][2 * h + 1] = packlh(tanh_apx(p2), tanh_apx(p3));
            }
        }
    }
}

__global__ void __launch_bounds__(THREADS, 1)
deq_mma_kernel(const float* __restrict__ x,
               const float* __restrict__ Aw,
               const float* __restrict__ Ab,
               const float* __restrict__ Bw,
               const float* __restrict__ Bb,
               const float* __restrict__ hw,
               const float* __restrict__ hb,
               float* __restrict__ out,
               int ntiles)
{
    extern __shared__ char smem[];
    const int tid = threadIdx.x;

    // ---- one-time staging: B (bf16, padded rows), h, Aw, Ab+Bb ----
    #pragma unroll 4
    for (int idx = tid; idx < 128 * 128; idx += THREADS) {
        int i = idx >> 7, j = idx & 127;
        *(__nv_bfloat16*)(smem + SM_B + i * LDB_B + j * 2) = __float2bfloat16(Bw[idx]);
    }
    if (tid < 128) {
        ((float*)(smem + SM_H))[tid]  = hw[tid];
        ((float*)(smem + SM_AB))[tid] = Ab[tid] + Bb[tid];
    }
    {   // Aw: 128 rows x 4 floats = 128 float4
        float4* awv = (float4*)(smem + SM_AW);
        if (tid < 128) awv[tid] = ((const float4*)Aw)[tid];
    }

    // ---- per-thread constants ----
    const int lane = tid & 31, wid = tid >> 5;
    const int qr = lane >> 2, qc = lane & 3;
    const int rb = wid * 16;
    const float2* c2   = (const float2*)(smem + SM_C);
    const float2* c2w  = c2 + (rb + qr) * (LDC_F / 2);
    const float2* c2w8 = c2w + 8 * (LDC_F / 2);
    const float2* h2   = (const float2*)(smem + SM_H);
    const float*  abv  = (const float*)(smem + SM_AB);
    const float4* awv  = (const float4*)(smem + SM_AW);
    const uint32_t sb  = (uint32_t)__cvta_generic_to_shared(smem);
    const uint32_t bb  = sb + SM_B + (uint32_t)(lane & 7) * LDB_B + (uint32_t)(lane >> 3) * 16;
    const float hb0 = hb[0];

    const int cr  = tid >> 1;           // c-compute: this thread's row
    const int ci0 = (tid & 1) << 6;     // and its half of the state dim
    float* crow = (float*)(smem + SM_C) + cr * LDC_F;

    for (int tile = blockIdx.x; tile < ntiles; tile += gridDim.x) {
        const int row0 = tile * 128;

        // ---- c = x A^T + (A_b + B_b) for this tile ----
        __syncthreads();   // previous tile's GEMM reads of c are done
        {
            float4 xv = ((const float4*)x)[row0 + cr];
            #pragma unroll 8
            for (int k = 0; k < 64; ++k) {
                int i = ci0 + k;
                float4 a = awv[i];
                crow[i] = abv[i] + xv.x * a.x + xv.y * a.y + xv.z * a.z + xv.w * a.w;
            }
        }
        __syncthreads();

        // ---- z1 = tanh(c) into A fragments ----
        uint32_t A[8][4], An[8][4];
        #pragma unroll
        for (int kt = 0; kt < 8; ++kt) {
            float2 u0 = c2w [8 * kt + qc];
            float2 u1 = c2w8[8 * kt + qc];
            float2 u2 = c2w [8 * kt + 4 + qc];
            float2 u3 = c2w8[8 * kt + 4 + qc];
            A[kt][0] = packlh(tanh_apx(u0.x), tanh_apx(u0.y));
            A[kt][1] = packlh(tanh_apx(u1.x), tanh_apx(u1.y));
            A[kt][2] = packlh(tanh_apx(u2.x), tanh_apx(u2.y));
            A[kt][3] = packlh(tanh_apx(u3.x), tanh_apx(u3.y));
        }

        // ---- 3 GEMM iterations (z2, z3, z4); last fuses y = z4 . h ----
        float y0 = 0.f, y1 = 0.f;
        gemm_iter<false>(bb, c2w, c2w8, h2, A,  An, y0, y1, qc);
        gemm_iter<false>(bb, c2w, c2w8, h2, An, A,  y0, y1, qc);
        gemm_iter<true >(bb, c2w, c2w8, h2, A,  An, y0, y1, qc);

        // ---- reduce y across the 4 lanes sharing a row, write out ----
        y0 += __shfl_xor_sync(0xffffffffu, y0, 1);
        y0 += __shfl_xor_sync(0xffffffffu, y0, 2);
        y1 += __shfl_xor_sync(0xffffffffu, y1, 1);
        y1 += __shfl_xor_sync(0xffffffffu, y1, 2);
        if (qc == 0) {
            out[row0 + rb + qr]     = y0 + hb0;
            out[row0 + rb + qr + 8] = y1 + hb0;
        }
    }
}

extern "C" void kernel_launch(void* const* d_in, const int* in_sizes, int n_in,
                              void* d_out, int out_size) {
    const float* x  = (const float*)d_in[0];
    const float* Aw = (const float*)d_in[1];
    const float* Ab = (const float*)d_in[2];
    const float* Bw = (const float*)d_in[3];
    const float* Bb = (const float*)d_in[4];
    const float* hw = (const float*)d_in[5];
    const float* hb = (const float*)d_in[6];
    float* out = (float*)d_out;

    int batch  = in_sizes[0] / 4;   // x is [batch, 4]
    int ntiles = batch / 128;       // 1024
    int grid   = 148;               // persistent: one CTA per SM

    cudaFuncSetAttribute(deq_mma_kernel,
                         cudaFuncAttributeMaxDynamicSharedMemorySize,
                         SM_TOTAL);
    deq_mma_kernel<<<grid, THREADS, SM_TOTAL>>>(x, Aw, Ab, Bw, Bb, hw, hb, out, ntiles);
}